// round 15
// baseline (speedup 1.0000x reference)
#include <cuda_runtime.h>
#include <stdint.h>

// AND-tree over last dim of (ROWS, 1024) binary float matrix.
// out[row] = 1.0f iff all 1024 elements == 1.0f (bit pattern 0x3F800000).
//
// Final configuration. Session findings (R2-R14):
//  - Cold path is limited by per-DRAM-line touch rate: 65536 rows x >=1
//    scattered line each (~8.4MB effective) ~= 6us regardless of probe size,
//    caching policy (__ldcs tested), address stagger (tested), or SM geometry
//    (tested). This is a hardware floor for the mandatory gather.
//  - Timed (graph-replay, warm-L2) duration is pinned at 6.66-6.91us across
//    all variants -> dominated by fixed replay/launch overhead, kernel
//    internals already sub-floor.
// This version minimizes the remaining structural terms: 512 small CTAs
// (128 thr) for minimal per-CTA ramp + full 148-SM coverage, default-cached
// 32B probe (L2-resident across replays, MLP=2, survival 2^-8), and
// warp-cooperative one-round survivor resolution (exact full-row recheck).

static constexpr int ROW_U4 = 1024 / 4;            // 256 uint4 per row
static constexpr unsigned ONE_BITS = 0x3F800000u;  // bit pattern of 1.0f
static constexpr int THREADS = 128;

__device__ __forceinline__ bool all_ones(uint4 v) {
    return v.x == ONE_BITS && v.y == ONE_BITS && v.z == ONE_BITS && v.w == ONE_BITS;
}

__global__ __launch_bounds__(THREADS) void vec_and_tree_kernel(
    const uint4* __restrict__ x, float* __restrict__ out, int rows)
{
    int row = blockIdx.x * THREADS + threadIdx.x;
    row = row < rows ? row : rows - 1;       // branchless clamp (benign dup)
    const int lane = threadIdx.x & 31;

    const uint4* rp = x + (size_t)row * ROW_U4;

    // Probe: 32B (two uint4), default caching so the 8.4MB probe footprint
    // stays L2-resident across graph replays. Stagger sweeps bits [7:12) of
    // the address across rows (harmless; keeps slices/banks spread).
    const int off = (row & 31) * 8;
    uint4 a = rp[off + 0];
    uint4 b = rp[off + 1];
    bool ok = all_ones(a) & all_ones(b);

    // Survivors (prob 2^-8/row, ~1 per 8 warps): warp-cooperative full-row
    // recheck (superset of probe -> exact), one parallel DRAM/L2 round.
    unsigned surv = __ballot_sync(0xFFFFFFFFu, ok);
    while (surv) {
        const int l = __ffs(surv) - 1;
        surv &= surv - 1;
        const int srow = __shfl_sync(0xFFFFFFFFu, row, l);
        const uint4* sp = x + (size_t)srow * ROW_U4;

        bool lok = true;
        #pragma unroll
        for (int i = 0; i < ROW_U4 / 32; i++) {     // 8 independent loads, MLP=8
            lok &= all_ones(__ldcs(sp + i * 32 + lane));  // streaming: don't evict probes
        }
        const bool rok = __all_sync(0xFFFFFFFFu, lok);
        if (lane == l) ok = rok;
    }

    out[row] = ok ? 1.0f : 0.0f;
}

extern "C" void kernel_launch(void* const* d_in, const int* in_sizes, int n_in,
                              void* d_out, int out_size)
{
    const uint4* x = (const uint4*)d_in[0];  // float32 bits reinterpreted
    float* out = (float*)d_out;

    const int rows = out_size;                              // 65536
    const int blocks = (rows + THREADS - 1) / THREADS;      // 512

    vec_and_tree_kernel<<<blocks, THREADS>>>(x, out, rows);
}

// round 16
// speedup vs baseline: 1.0625x; 1.0625x over previous
#include <cuda_runtime.h>
#include <stdint.h>

// AND-tree over last dim of (ROWS, 1024) binary float matrix.
// out[row] = 1.0f iff all 1024 elements == 1.0f (bit pattern 0x3F800000).
//
// R16: COALESCED high-MLP probe — the one untested corner of the design
// space. All rounds since R3 probed thread-per-row: each LDG's 32 lanes hit
// 32 distinct 128B lines (4KB apart) = 32 L1tex wavefronts per instruction
// (~262K wavefronts chip-wide for a 64B probe). R2 was coalesced but MLP=1.
// Here one warp owns R=8 consecutive rows; lane loads word `lane` of each
// row -> 8 independent, perfectly coalesced LDG.32 (1 wavefront each,
// MLP=8). 4x fewer L1tex wavefronts, full-line 128B probe (survival 2^-32
// -> ~zero survivors chip-wide), same mandatory 65536-line DRAM footprint.
// Survivor fallback: warp-cooperative full-row recheck (exact).

static constexpr int ROW_LEN = 1024;               // words per row
static constexpr unsigned ONE_BITS = 0x3F800000u; // bit pattern of 1.0f
static constexpr int R = 8;                        // rows per warp
static constexpr int THREADS = 256;                // 8 warps per block

__global__ __launch_bounds__(THREADS) void vec_and_tree_kernel(
    const unsigned* __restrict__ x, float* __restrict__ out, int rows)
{
    const int warp_global = (blockIdx.x * THREADS + threadIdx.x) >> 5;
    const int lane = threadIdx.x & 31;
    int base_row = warp_global * R;
    if (base_row >= rows) return;                  // rows % (R*warps/blk) == 0

    // Phase 1: R independent coalesced probes (first 128B of each row),
    // all issued before any test -> MLP = R, 1 L1tex wavefront per load.
    unsigned v[R];
    #pragma unroll
    for (int k = 0; k < R; k++)
        v[k] = x[(size_t)(base_row + k) * ROW_LEN + lane];

    // Phase 2: one vote per row; 128b probe -> survival 2^-32 per row.
    unsigned m = 0;                                // warp-uniform result bitmask
    #pragma unroll
    for (int k = 0; k < R; k++) {
        bool ok = __all_sync(0xFFFFFFFFu, v[k] == ONE_BITS);
        if (ok) {
            // Essentially-never path: exact full-row recheck, coalesced,
            // 31 independent loads (words 32..1023).
            const unsigned* rp = x + (size_t)(base_row + k) * ROW_LEN;
            bool lok = true;
            #pragma unroll 1
            for (int i = 1; i < ROW_LEN / 32; i++)
                lok &= (rp[i * 32 + lane] == ONE_BITS);
            ok = __all_sync(0xFFFFFFFFu, lok);
        }
        m |= (ok ? 1u : 0u) << k;
    }

    // Phase 3: coalesced output — lanes 0..R-1 write the R consecutive rows.
    if (lane < R)
        out[base_row + lane] = (m >> lane) & 1u ? 1.0f : 0.0f;
}

extern "C" void kernel_launch(void* const* d_in, const int* in_sizes, int n_in,
                              void* d_out, int out_size)
{
    const unsigned* x = (const unsigned*)d_in[0];  // float32 bits reinterpreted
    float* out = (float*)d_out;

    const int rows = out_size;                     // 65536
    const int rows_per_block = (THREADS / 32) * R; // 64
    const int blocks = (rows + rows_per_block - 1) / rows_per_block;  // 1024

    vec_and_tree_kernel<<<blocks, THREADS>>>(x, out, rows);
}